// round 3
// baseline (speedup 1.0000x reference)
#include <cuda_runtime.h>

typedef unsigned long long u64;

#define TPB 256

// ---------- packed f32x2 helpers (sm_103a) ----------
__device__ __forceinline__ void fma2(u64 &d, u64 a, u64 b) {
    asm("fma.rn.f32x2 %0, %1, %2, %0;" : "+l"(d) : "l"(a), "l"(b));
}
__device__ __forceinline__ float unpack_add(u64 v) {
    float lo, hi;
    asm("mov.b64 {%0,%1}, %2;" : "=f"(lo), "=f"(hi) : "l"(v));
    return lo + hi;
}

// ---------- shared memory layout (floats) ----------
#define LD64 68
#define LD32 36
#define OFF_X    0                       // 64x68: xf -> cat(out_pan|out_color) -> v2(scaled)
#define OFF_P    (OFF_X + 64*LD64)       // 64x36: pan
#define OFF_PQ   (OFF_P + 64*LD32)       // 64x36: pan_q (kept until cos)
#define OFF_PK   (OFF_PQ + 64*LD32)      // 64x36: pan_k
#define OFF_V1   (OFF_PK + 64*LD32)      // 64x68: v1 -> out(inner) -> final
#define OFF_Q1   (OFF_V1 + 64*LD64)     // 64x36: q1c
#define OFF_K1   (OFF_Q1 + 64*LD32)      // 64x36: k1c -> k2
#define OFF_W    (OFF_K1 + 64*LD32)      // 64x68: weight scratch
#define OFF_COS  (OFF_W + 64*LD64)       // 512:   cos[h][t]
#define SMEM_FLOATS (OFF_COS + 512)      // 25088 floats = 100352 B

// cooperative copy of W[NO][KA] (row-major global) into padded smem scratch
template<int NO, int KA>
__device__ __forceinline__ void loadW(const float* __restrict__ g, float* __restrict__ s, int tid) {
    constexpr int LDW = KA + 4;
    constexpr int SH  = (KA == 64) ? 6 : 5;
    constexpr int ITER = (NO * KA) / TPB;
    #pragma unroll
    for (int r = 0; r < ITER; ++r) {
        int e = tid + r * TPB;
        int o = e >> SH, k = e & (KA - 1);
        s[o * LDW + k] = g[e];
    }
}

// O[64][NO] = A[64][KA] @ W[NO][KA]^T   (all smem, padded pitches KA+4 / NO+4)
// 256 threads; thread tile = 4 tokens x TN outputs (outputs strided by 16 for
// conflict-free W reads); inner product packed as f32x2 pairs along K.
template<int NO, int KA>
__device__ __forceinline__ void gemm(const float* __restrict__ A, const float* __restrict__ W,
                                     float* __restrict__ O, int tid)
{
    constexpr int LDA = KA + 4, LDW = KA + 4, LDO = NO + 4;
    constexpr int TN  = NO / 16;
    const int ot = tid & 15;
    const int t0 = (tid >> 4) * 4;

    u64 acc[4][TN];
    #pragma unroll
    for (int i = 0; i < 4; ++i)
        #pragma unroll
        for (int j = 0; j < TN; ++j) acc[i][j] = 0ull;

    #pragma unroll
    for (int k = 0; k < KA; k += 4) {
        ulonglong2 a[4], w[TN];
        #pragma unroll
        for (int i = 0; i < 4; ++i)
            a[i] = *(const ulonglong2*)(A + (t0 + i) * LDA + k);
        #pragma unroll
        for (int j = 0; j < TN; ++j)
            w[j] = *(const ulonglong2*)(W + (ot + 16 * j) * LDW + k);
        #pragma unroll
        for (int i = 0; i < 4; ++i)
            #pragma unroll
            for (int j = 0; j < TN; ++j) {
                fma2(acc[i][j], a[i].x, w[j].x);
                fma2(acc[i][j], a[i].y, w[j].y);
            }
    }
    #pragma unroll
    for (int i = 0; i < 4; ++i)
        #pragma unroll
        for (int j = 0; j < TN; ++j)
            O[(t0 + i) * LDO + ot + 16 * j] = unpack_add(acc[i][j]);
}

__global__ void __launch_bounds__(TPB, 2)
in2ma_kernel(const float* __restrict__ x,        const float* __restrict__ pan,
             const float* __restrict__ Wpq,      const float* __restrict__ Wpk,
             const float* __restrict__ Wv1,      const float* __restrict__ Wv2,
             const float* __restrict__ Wk2,      const float* __restrict__ Wq1c,
             const float* __restrict__ Wk1c,     const float* __restrict__ Wio,
             const float* __restrict__ Wto,      const float* __restrict__ pos_inner,
             const float* __restrict__ pos_color, float* __restrict__ out)
{
    extern __shared__ float sm[];
    const int tid = threadIdx.x;
    const int wb  = blockIdx.x;
    const int b   = wb >> 10;
    const int hi  = (wb >> 5) & 31;
    const int wi  = wb & 31;

    const int cbase = (b * 64) * 65536 + (hi * 8) * 256 + wi * 8;   // 64-channel tensors
    const int pbase = (b * 32) * 65536 + (hi * 8) * 256 + wi * 8;   // 32-channel pan

    // ---- stage window: xf[64tok][64ch], pan[64tok][32ch] ----
    #pragma unroll
    for (int r = 0; r < 16; ++r) {
        int e = tid + r * TPB;
        int c = e >> 6, t = e & 63;
        sm[OFF_X + t * LD64 + c] = x[cbase + c * 65536 + (t >> 3) * 256 + (t & 7)];
    }
    #pragma unroll
    for (int r = 0; r < 8; ++r) {
        int e = tid + r * TPB;
        int c = e >> 6, t = e & 63;
        sm[OFF_P + t * LD32 + c] = pan[pbase + c * 65536 + (t >> 3) * 256 + (t & 7)];
    }

    // ---- projection GEMMs ----
    loadW<32, 32>(Wpq, sm + OFF_W, tid);
    __syncthreads();
    gemm<32, 32>(sm + OFF_P, sm + OFF_W, sm + OFF_PQ, tid);
    __syncthreads();
    loadW<32, 32>(Wpk, sm + OFF_W, tid);
    __syncthreads();
    gemm<32, 32>(sm + OFF_P, sm + OFF_W, sm + OFF_PK, tid);
    __syncthreads();
    loadW<64, 64>(Wv1, sm + OFF_W, tid);
    __syncthreads();
    gemm<64, 64>(sm + OFF_X, sm + OFF_W, sm + OFF_V1, tid);
    __syncthreads();
    loadW<32, 64>(Wq1c, sm + OFF_W, tid);
    __syncthreads();
    gemm<32, 64>(sm + OFF_X, sm + OFF_W, sm + OFF_Q1, tid);
    __syncthreads();
    loadW<32, 64>(Wk1c, sm + OFF_W, tid);
    __syncthreads();
    gemm<32, 64>(sm + OFF_X, sm + OFF_W, sm + OFF_K1, tid);
    __syncthreads();

    const float scale = 0.35355339059327373f;   // (SPA_INNER/HEADS)^-0.5 = 8^-0.5

    // ---- pan window attention: heads=8, dhead=4, seq=64 ----
    // rows (h,i); thread handles 2 rows. single-pass softmax (scores are O(10), exp safe)
    #pragma unroll
    for (int rr0 = 0; rr0 < 2; ++rr0) {
        int rr = tid + rr0 * TPB;
        int h = rr >> 6, i = rr & 63;
        const float* q = sm + OFF_PQ + i * LD32 + h * 4;
        float q0 = q[0] * scale, q1 = q[1] * scale, q2 = q[2] * scale, q3 = q[3] * scale;
        const float* pi = pos_inner + (h * 64 + i) * 64;
        float l = 0.f, o0 = 0.f, o1 = 0.f, o2 = 0.f, o3 = 0.f;
        #pragma unroll 4
        for (int j = 0; j < 64; ++j) {
            float4 kk = *(const float4*)(sm + OFF_PK + j * LD32 + h * 4);
            float s = q0 * kk.x + q1 * kk.y + q2 * kk.z + q3 * kk.w + pi[j];
            float e = __expf(s);
            l += e;
            float4 vv = *(const float4*)(sm + OFF_V1 + j * LD64 + h * 4); // v1_pan cols 0..31
            o0 += e * vv.x; o1 += e * vv.y; o2 += e * vv.z; o3 += e * vv.w;
        }
        float inv = 1.f / l;
        float* oc = sm + OFF_X + i * LD64 + h * 4;   // cat cols [0,32): out_pan
        oc[0] = o0 * inv; oc[1] = o1 * inv; oc[2] = o2 * inv; oc[3] = o3 * inv;
    }

    // ---- color attention: heads=8, n=32 (channels), inner dim d=8 (tokens of head) ----
    {
        int h = tid >> 5, i = tid & 31;
        float qd[8];
        #pragma unroll
        for (int d = 0; d < 8; ++d)
            qd[d] = sm[OFF_Q1 + (h * 8 + d) * LD32 + i] * scale;
        const float* pc = pos_color + (h * 32 + i) * 32;
        float l = 0.f;
        float o[8] = {0.f, 0.f, 0.f, 0.f, 0.f, 0.f, 0.f, 0.f};
        #pragma unroll 4
        for (int j = 0; j < 32; ++j) {
            float s = pc[j];
            #pragma unroll
            for (int d = 0; d < 8; ++d)
                s += qd[d] * sm[OFF_K1 + (h * 8 + d) * LD32 + j];
            float e = __expf(s);
            l += e;
            #pragma unroll
            for (int d = 0; d < 8; ++d)
                o[d] += e * sm[OFF_V1 + (h * 8 + d) * LD64 + 32 + j]; // v1_color cols 32..63
        }
        float inv = 1.f / l;
        #pragma unroll
        for (int d = 0; d < 8; ++d)
            sm[OFF_X + (h * 8 + d) * LD64 + 32 + i] = o[d] * inv;   // cat cols [32,64)
    }
    __syncthreads();

    // ---- out = cat @ Wio^T -> OFF_V1 ----
    loadW<64, 64>(Wio, sm + OFF_W, tid);
    __syncthreads();
    gemm<64, 64>(sm + OFF_X, sm + OFF_W, sm + OFF_V1, tid);
    __syncthreads();
    // ---- v2 = out @ Wv2^T -> OFF_X ----
    loadW<64, 64>(Wv2, sm + OFF_W, tid);
    __syncthreads();
    gemm<64, 64>(sm + OFF_V1, sm + OFF_W, sm + OFF_X, tid);
    __syncthreads();
    // ---- k2 = out @ Wk2^T -> OFF_K1 ----
    loadW<32, 64>(Wk2, sm + OFF_W, tid);
    __syncthreads();
    gemm<32, 64>(sm + OFF_V1, sm + OFF_W, sm + OFF_K1, tid);
    __syncthreads();

    // ---- inter attention: cosine gate per (head, token) ----
    #pragma unroll
    for (int rr0 = 0; rr0 < 2; ++rr0) {
        int rr = tid + rr0 * TPB;
        int h = rr >> 6, t = rr & 63;
        const float* q = sm + OFF_PQ + t * LD32 + h * 4;
        const float* k = sm + OFF_K1 + t * LD32 + h * 4;
        float dot = 0.f, qq = 0.f, kk = 0.f;
        #pragma unroll
        for (int d = 0; d < 4; ++d) {
            dot += q[d] * k[d];
            qq  += q[d] * q[d];
            kk  += k[d] * k[d];
        }
        sm[OFF_COS + h * 64 + t] = dot * rsqrtf(qq * kk);
    }
    __syncthreads();
    // scale v2 in place: v2[t][c] *= cos[c>>3][t]
    #pragma unroll
    for (int r = 0; r < 16; ++r) {
        int e = tid + r * TPB;
        int t = e >> 6, c = e & 63;
        sm[OFF_X + t * LD64 + c] *= sm[OFF_COS + (c >> 3) * 64 + t];
    }
    loadW<64, 64>(Wto, sm + OFF_W, tid);
    __syncthreads();

    // ---- final = (cos*v2) @ Wto^T -> OFF_V1 ----
    gemm<64, 64>(sm + OFF_X, sm + OFF_W, sm + OFF_V1, tid);
    __syncthreads();

    // ---- un-partition and store ----
    #pragma unroll
    for (int r = 0; r < 16; ++r) {
        int e = tid + r * TPB;
        int c = e >> 6, t = e & 63;
        out[cbase + c * 65536 + (t >> 3) * 256 + (t & 7)] = sm[OFF_V1 + t * LD64 + c];
    }
}

extern "C" void kernel_launch(void* const* d_in, const int* in_sizes, int n_in,
                              void* d_out, int out_size)
{
    (void)in_sizes; (void)n_in; (void)out_size;
    const size_t smem_bytes = SMEM_FLOATS * sizeof(float);
    cudaFuncSetAttribute(in2ma_kernel, cudaFuncAttributeMaxDynamicSharedMemorySize,
                         (int)smem_bytes);
    in2ma_kernel<<<4096, TPB, smem_bytes>>>(
        (const float*)d_in[0],  // x
        (const float*)d_in[1],  // pan_feature
        (const float*)d_in[2],  // W_pan_q
        (const float*)d_in[3],  // W_pan_k
        (const float*)d_in[4],  // W_v1
        (const float*)d_in[5],  // W_v2
        (const float*)d_in[6],  // W_k2
        (const float*)d_in[7],  // W_q1c
        (const float*)d_in[8],  // W_k1c
        (const float*)d_in[9],  // W_inner_out
        (const float*)d_in[10], // W_inter_out
        (const float*)d_in[11], // pos_inner
        (const float*)d_in[12], // pos_color
        (float*)d_out);
}

// round 5
// speedup vs baseline: 1.8438x; 1.8438x over previous
#include <cuda_runtime.h>

typedef unsigned long long u64;

#define TPB 256

// ---------- packed f32x2 helpers (sm_103a) ----------
__device__ __forceinline__ void fma2(u64 &d, u64 a, u64 b) {
    asm("fma.rn.f32x2 %0, %1, %2, %0;" : "+l"(d) : "l"(a), "l"(b));
}
__device__ __forceinline__ float unpack_add(u64 v) {
    float lo, hi;
    asm("mov.b64 {%0,%1}, %2;" : "=f"(lo), "=f"(hi) : "l"(v));
    return lo + hi;
}

// ---------- transposed positional tables (filled by pre-kernel) ----------
// g_posT_inner[h][j][i], g_posT_color[h][j][i] — lanes (consecutive i) coalesce.
__device__ float g_posT_inner[8 * 64 * 64];
__device__ float g_posT_color[8 * 32 * 32];

__global__ void transpose_pos_kernel(const float* __restrict__ pos_inner,
                                     const float* __restrict__ pos_color)
{
    int t = blockIdx.x * blockDim.x + threadIdx.x;
    if (t < 8 * 64 * 64) {
        int h = t >> 12, i = (t >> 6) & 63, j = t & 63;   // src (h,i,j)
        g_posT_inner[(h << 12) | (j << 6) | i] = pos_inner[t];
    }
    if (t < 8 * 32 * 32) {
        int h = t >> 10, i = (t >> 5) & 31, j = t & 31;
        g_posT_color[(h << 10) | (j << 5) | i] = pos_color[t];
    }
}

// ---------- shared memory layout (floats) ----------
#define LD64 68
#define LD32 36
#define OFF_X    0                       // 64x68: xf -> cat(out_pan|out_color) -> v2(scaled)
#define OFF_P    (OFF_X + 64*LD64)       // 64x36: pan
#define OFF_PQ   (OFF_P + 64*LD32)       // 64x36: pan_q (kept until cos)
#define OFF_PK   (OFF_PQ + 64*LD32)      // 64x36: pan_k
#define OFF_V1   (OFF_PK + 64*LD32)      // 64x68: v1 -> out(inner) -> final
#define OFF_Q1   (OFF_V1 + 64*LD64)     // 64x36: q1c
#define OFF_K1   (OFF_Q1 + 64*LD32)      // 64x36: k1c -> k2
#define OFF_W    (OFF_K1 + 64*LD32)      // 64x68: weight scratch
#define OFF_COS  (OFF_W + 64*LD64)       // 512:   cos[h][t]
#define SMEM_FLOATS (OFF_COS + 512)      // 25088 floats = 100352 B

// cooperative copy of W[NO][KA] (row-major global) into padded smem scratch
template<int NO, int KA>
__device__ __forceinline__ void loadW(const float* __restrict__ g, float* __restrict__ s, int tid) {
    constexpr int LDW = KA + 4;
    constexpr int SH  = (KA == 64) ? 6 : 5;
    constexpr int ITER = (NO * KA) / TPB;
    #pragma unroll
    for (int r = 0; r < ITER; ++r) {
        int e = tid + r * TPB;
        int o = e >> SH, k = e & (KA - 1);
        s[o * LDW + k] = g[e];
    }
}

// O[64][NO] = A[64][KA] @ W[NO][KA]^T   (all smem, padded pitches KA+4 / NO+4)
template<int NO, int KA>
__device__ __forceinline__ void gemm(const float* __restrict__ A, const float* __restrict__ W,
                                     float* __restrict__ O, int tid)
{
    constexpr int LDA = KA + 4, LDW = KA + 4, LDO = NO + 4;
    constexpr int TN  = NO / 16;
    const int ot = tid & 15;
    const int t0 = (tid >> 4) * 4;

    u64 acc[4][TN];
    #pragma unroll
    for (int i = 0; i < 4; ++i)
        #pragma unroll
        for (int j = 0; j < TN; ++j) acc[i][j] = 0ull;

    #pragma unroll
    for (int k = 0; k < KA; k += 4) {
        ulonglong2 a[4], w[TN];
        #pragma unroll
        for (int i = 0; i < 4; ++i)
            a[i] = *(const ulonglong2*)(A + (t0 + i) * LDA + k);
        #pragma unroll
        for (int j = 0; j < TN; ++j)
            w[j] = *(const ulonglong2*)(W + (ot + 16 * j) * LDW + k);
        #pragma unroll
        for (int i = 0; i < 4; ++i)
            #pragma unroll
            for (int j = 0; j < TN; ++j) {
                fma2(acc[i][j], a[i].x, w[j].x);
                fma2(acc[i][j], a[i].y, w[j].y);
            }
    }
    #pragma unroll
    for (int i = 0; i < 4; ++i)
        #pragma unroll
        for (int j = 0; j < TN; ++j)
            O[(t0 + i) * LDO + ot + 16 * j] = unpack_add(acc[i][j]);
}

__global__ void __launch_bounds__(TPB, 2)
in2ma_kernel(const float* __restrict__ x,        const float* __restrict__ pan,
             const float* __restrict__ Wpq,      const float* __restrict__ Wpk,
             const float* __restrict__ Wv1,      const float* __restrict__ Wv2,
             const float* __restrict__ Wk2,      const float* __restrict__ Wq1c,
             const float* __restrict__ Wk1c,     const float* __restrict__ Wio,
             const float* __restrict__ Wto,      float* __restrict__ out)
{
    extern __shared__ float sm[];
    const int tid = threadIdx.x;
    const int wb  = blockIdx.x;
    const int b   = wb >> 10;
    const int hi  = (wb >> 5) & 31;
    const int wi  = wb & 31;

    const int cbase = (b * 64) * 65536 + (hi * 8) * 256 + wi * 8;   // 64-channel tensors
    const int pbase = (b * 32) * 65536 + (hi * 8) * 256 + wi * 8;   // 32-channel pan

    // ---- stage window: xf[64tok][64ch], pan[64tok][32ch] ----
    #pragma unroll
    for (int r = 0; r < 16; ++r) {
        int e = tid + r * TPB;
        int c = e >> 6, t = e & 63;
        sm[OFF_X + t * LD64 + c] = x[cbase + c * 65536 + (t >> 3) * 256 + (t & 7)];
    }
    #pragma unroll
    for (int r = 0; r < 8; ++r) {
        int e = tid + r * TPB;
        int c = e >> 6, t = e & 63;
        sm[OFF_P + t * LD32 + c] = pan[pbase + c * 65536 + (t >> 3) * 256 + (t & 7)];
    }

    // ---- projection GEMMs ----
    loadW<32, 32>(Wpq, sm + OFF_W, tid);
    __syncthreads();
    gemm<32, 32>(sm + OFF_P, sm + OFF_W, sm + OFF_PQ, tid);
    __syncthreads();
    loadW<32, 32>(Wpk, sm + OFF_W, tid);
    __syncthreads();
    gemm<32, 32>(sm + OFF_P, sm + OFF_W, sm + OFF_PK, tid);
    __syncthreads();
    loadW<64, 64>(Wv1, sm + OFF_W, tid);
    __syncthreads();
    gemm<64, 64>(sm + OFF_X, sm + OFF_W, sm + OFF_V1, tid);
    __syncthreads();
    loadW<32, 64>(Wq1c, sm + OFF_W, tid);
    __syncthreads();
    gemm<32, 64>(sm + OFF_X, sm + OFF_W, sm + OFF_Q1, tid);
    __syncthreads();
    loadW<32, 64>(Wk1c, sm + OFF_W, tid);
    __syncthreads();
    gemm<32, 64>(sm + OFF_X, sm + OFF_W, sm + OFF_K1, tid);
    __syncthreads();

    const float scale = 0.35355339059327373f;   // (SPA_INNER/HEADS)^-0.5 = 8^-0.5

    // ---- pan window attention: heads=8, dhead=4, seq=64 ----
    // thread owns row (h,i); K/V smem reads are warp-uniform broadcasts;
    // pos read from transposed table: lanes (consecutive i) coalesce.
    #pragma unroll
    for (int rr0 = 0; rr0 < 2; ++rr0) {
        int rr = tid + rr0 * TPB;
        int h = rr >> 6, i = rr & 63;
        const float* q = sm + OFF_PQ + i * LD32 + h * 4;
        float q0 = q[0] * scale, q1 = q[1] * scale, q2 = q[2] * scale, q3 = q[3] * scale;
        const float* piT = g_posT_inner + (h << 12) + i;   // + (j<<6)
        float l = 0.f, o0 = 0.f, o1 = 0.f, o2 = 0.f, o3 = 0.f;
        #pragma unroll 4
        for (int j = 0; j < 64; ++j) {
            float4 kk = *(const float4*)(sm + OFF_PK + j * LD32 + h * 4);
            float s = q0 * kk.x + q1 * kk.y + q2 * kk.z + q3 * kk.w + piT[j << 6];
            float e = __expf(s);
            l += e;
            float4 vv = *(const float4*)(sm + OFF_V1 + j * LD64 + h * 4); // v1_pan cols 0..31
            o0 += e * vv.x; o1 += e * vv.y; o2 += e * vv.z; o3 += e * vv.w;
        }
        float inv = 1.f / l;
        float* oc = sm + OFF_X + i * LD64 + h * 4;   // cat cols [0,32): out_pan
        oc[0] = o0 * inv; oc[1] = o1 * inv; oc[2] = o2 * inv; oc[3] = o3 * inv;
    }

    // ---- color attention: heads=8, n=32 (channels), inner dim d=8 (tokens of head) ----
    {
        int h = tid >> 5, i = tid & 31;
        float qd[8];
        #pragma unroll
        for (int d = 0; d < 8; ++d)
            qd[d] = sm[OFF_Q1 + (h * 8 + d) * LD32 + i] * scale;
        const float* pcT = g_posT_color + (h << 10) + i;   // + (j<<5)
        float l = 0.f;
        float o[8] = {0.f, 0.f, 0.f, 0.f, 0.f, 0.f, 0.f, 0.f};
        #pragma unroll 4
        for (int j = 0; j < 32; ++j) {
            float s = pcT[j << 5];
            #pragma unroll
            for (int d = 0; d < 8; ++d)
                s += qd[d] * sm[OFF_K1 + (h * 8 + d) * LD32 + j];
            float e = __expf(s);
            l += e;
            #pragma unroll
            for (int d = 0; d < 8; ++d)
                o[d] += e * sm[OFF_V1 + (h * 8 + d) * LD64 + 32 + j]; // v1_color cols 32..63
        }
        float inv = 1.f / l;
        #pragma unroll
        for (int d = 0; d < 8; ++d)
            sm[OFF_X + (h * 8 + d) * LD64 + 32 + i] = o[d] * inv;   // cat cols [32,64)
    }
    __syncthreads();

    // ---- out = cat @ Wio^T -> OFF_V1 ----
    loadW<64, 64>(Wio, sm + OFF_W, tid);
    __syncthreads();
    gemm<64, 64>(sm + OFF_X, sm + OFF_W, sm + OFF_V1, tid);
    __syncthreads();
    // ---- v2 = out @ Wv2^T -> OFF_X ----
    loadW<64, 64>(Wv2, sm + OFF_W, tid);
    __syncthreads();
    gemm<64, 64>(sm + OFF_V1, sm + OFF_W, sm + OFF_X, tid);
    __syncthreads();
    // ---- k2 = out @ Wk2^T -> OFF_K1 ----
    loadW<32, 64>(Wk2, sm + OFF_W, tid);
    __syncthreads();
    gemm<32, 64>(sm + OFF_V1, sm + OFF_W, sm + OFF_K1, tid);
    __syncthreads();

    // ---- inter attention: cosine gate per (head, token) ----
    #pragma unroll
    for (int rr0 = 0; rr0 < 2; ++rr0) {
        int rr = tid + rr0 * TPB;
        int h = rr >> 6, t = rr & 63;
        const float* q = sm + OFF_PQ + t * LD32 + h * 4;
        const float* k = sm + OFF_K1 + t * LD32 + h * 4;
        float dot = 0.f, qq = 0.f, kk = 0.f;
        #pragma unroll
        for (int d = 0; d < 4; ++d) {
            dot += q[d] * k[d];
            qq  += q[d] * q[d];
            kk  += k[d] * k[d];
        }
        sm[OFF_COS + h * 64 + t] = dot * rsqrtf(qq * kk);
    }
    __syncthreads();
    // scale v2 in place: v2[t][c] *= cos[c>>3][t]
    #pragma unroll
    for (int r = 0; r < 16; ++r) {
        int e = tid + r * TPB;
        int t = e >> 6, c = e & 63;
        sm[OFF_X + t * LD64 + c] *= sm[OFF_COS + (c >> 3) * 64 + t];
    }
    loadW<64, 64>(Wto, sm + OFF_W, tid);
    __syncthreads();

    // ---- final = (cos*v2) @ Wto^T -> OFF_V1 ----
    gemm<64, 64>(sm + OFF_X, sm + OFF_W, sm + OFF_V1, tid);
    __syncthreads();

    // ---- un-partition and store ----
    #pragma unroll
    for (int r = 0; r < 16; ++r) {
        int e = tid + r * TPB;
        int c = e >> 6, t = e & 63;
        out[cbase + c * 65536 + (t >> 3) * 256 + (t & 7)] = sm[OFF_V1 + t * LD64 + c];
    }
}

extern "C" void kernel_launch(void* const* d_in, const int* in_sizes, int n_in,
                              void* d_out, int out_size)
{
    (void)in_sizes; (void)n_in; (void)out_size;

    // 1) transpose positional tables into __device__ scratch (coalesced reads later)
    transpose_pos_kernel<<<128, 256>>>((const float*)d_in[11],   // pos_inner
                                       (const float*)d_in[12]);  // pos_color

    // 2) main fused kernel
    const size_t smem_bytes = SMEM_FLOATS * sizeof(float);
    cudaFuncSetAttribute(in2ma_kernel, cudaFuncAttributeMaxDynamicSharedMemorySize,
                         (int)smem_bytes);
    in2ma_kernel<<<4096, TPB, smem_bytes>>>(
        (const float*)d_in[0],  // x
        (const float*)d_in[1],  // pan_feature
        (const float*)d_in[2],  // W_pan_q
        (const float*)d_in[3],  // W_pan_k
        (const float*)d_in[4],  // W_v1
        (const float*)d_in[5],  // W_v2
        (const float*)d_in[6],  // W_k2
        (const float*)d_in[7],  // W_q1c
        (const float*)d_in[8],  // W_k1c
        (const float*)d_in[9],  // W_inner_out
        (const float*)d_in[10], // W_inter_out
        (float*)d_out);
}